// round 4
// baseline (speedup 1.0000x reference)
#include <cuda_runtime.h>
#include <cstdint>

#define HID 16
#define NT 400000
#define ND 200000
#define NDEV 8

// concatenated degree/offset segments:
//   [0,NT)        dt   (data->tasks)
//   [NT,2NT)      devt (devices->tasks)
//   [2NT,3NT)     tto  (tasks->tasks to)
//   [3NT,4NT)     ttf  (tasks->tasks from)
//   [4NT,4NT+ND)  td   (tasks->data)
//   [4NT+ND, ...) devd (devices->data)
#define DEGN (4 * NT + 2 * ND)            // 2,000,000
#define ETOT 5400000                      // 1.6M+0.4M+0.8M+0.8M+1.6M+0.2M
#define EPB 2048
#define NBLK ((DEGN + EPB - 1) / EPB)     // 977

// ---------------- static scratch ----------------
__device__ __align__(16) int g_deg[DEGN];
__device__ __align__(16) int g_off[DEGN];
__device__ __align__(16) int g_cur[DEGN];
__device__ __align__(16) int g_srcbuf[ETOT];
__device__ int g_bsum[NBLK];
__device__ float g_agg_tdev[NDEV * 12];
__device__ float g_agg_ddev[NDEV * 8];

// ---------------- zero ----------------
__global__ void zero_deg() {
    int4 z = make_int4(0, 0, 0, 0);
    size_t n4 = DEGN / 4;
    for (size_t j = (size_t)blockIdx.x * blockDim.x + threadIdx.x; j < n4;
         j += (size_t)gridDim.x * blockDim.x)
        ((int4*)g_deg)[j] = z;
    size_t i = (size_t)blockIdx.x * blockDim.x + threadIdx.x;
    if (i < NDEV * 12) g_agg_tdev[i] = 0.f;
    if (i < NDEV * 8)  g_agg_ddev[i] = 0.f;
}

// ---------------- degree count ----------------
__global__ void count_edges(const int* __restrict__ ei, int E, int base) {
    int e = blockIdx.x * blockDim.x + threadIdx.x;
    if (e < E) atomicAdd(&g_deg[base + ei[E + e]], 1);
}

// ---------------- exclusive scan over g_deg (3 kernels) ----------------
__device__ __forceinline__ int warp_incl_scan(int v) {
#pragma unroll
    for (int d = 1; d < 32; d <<= 1) {
        int x = __shfl_up_sync(0xffffffffu, v, d);
        if ((threadIdx.x & 31) >= d) v += x;
    }
    return v;
}

__global__ void scan_partial() {   // 1024 threads, 2 elems each
    __shared__ int wsum[32];
    int t = threadIdx.x;
    size_t i0 = (size_t)blockIdx.x * EPB + 2 * t;
    int a0 = (i0 < DEGN) ? g_deg[i0] : 0;
    int a1 = (i0 + 1 < DEGN) ? g_deg[i0 + 1] : 0;
    int v = a0 + a1;
    int lane = t & 31, w = t >> 5;
    int s = warp_incl_scan(v);
    if (lane == 31) wsum[w] = s;
    __syncthreads();
    if (w == 0) {
        int ws = wsum[lane];
        ws = warp_incl_scan(ws);
        wsum[lane] = ws;
    }
    __syncthreads();
    int incl = s + (w > 0 ? wsum[w - 1] : 0);
    int excl = incl - v;
    if (i0 < DEGN) g_off[i0] = excl;
    if (i0 + 1 < DEGN) g_off[i0 + 1] = excl + a0;
    if (t == 1023) g_bsum[blockIdx.x] = incl;
}

__global__ void scan_bsum() {      // single block of 1024
    __shared__ int wsum[32];
    int t = threadIdx.x;
    int v = (t < NBLK) ? g_bsum[t] : 0;
    int lane = t & 31, w = t >> 5;
    int s = warp_incl_scan(v);
    if (lane == 31) wsum[w] = s;
    __syncthreads();
    if (w == 0) {
        int ws = wsum[lane];
        ws = warp_incl_scan(ws);
        wsum[lane] = ws;
    }
    __syncthreads();
    int incl = s + (w > 0 ? wsum[w - 1] : 0);
    if (t < NBLK) g_bsum[t] = incl - v;   // exclusive
}

__global__ void scan_add() {
    int add = g_bsum[blockIdx.x];
    size_t i = (size_t)blockIdx.x * EPB + threadIdx.x;
#pragma unroll
    for (int k = 0; k < 2; k++, i += 1024) {
        if (i < DEGN) {
            int o = g_off[i] + add;
            g_off[i] = o;
            g_cur[i] = o;
        }
    }
}

// ---------------- fill CSR src lists ----------------
__global__ void fill_edges(const int* __restrict__ ei, int E, int base) {
    int e = blockIdx.x * blockDim.x + threadIdx.x;
    if (e >= E) return;
    int s = ei[e];
    int d = ei[E + e];
    int pos = atomicAdd(&g_cur[base + d], 1);
    g_srcbuf[pos] = s;
}

// ---------------- device-dst relations: shared-mem scatter (tiny) ----------------
template <int D>
__global__ void scatter_dev(const float* __restrict__ xsrc, const int* __restrict__ ei,
                            int E, int which) {
    __shared__ float acc[NDEV * D];
    for (int i = threadIdx.x; i < NDEV * D; i += blockDim.x) acc[i] = 0.f;
    __syncthreads();
    for (int e = blockIdx.x * blockDim.x + threadIdx.x; e < E;
         e += gridDim.x * blockDim.x) {
        int s = ei[e];
        int d = ei[E + e];
        const float* xr = xsrc + (size_t)s * D;
#pragma unroll
        for (int k = 0; k < D; k++) atomicAdd(&acc[d * D + k], xr[k]);
    }
    __syncthreads();
    float* agg = (which == 2) ? g_agg_tdev : g_agg_ddev;
    for (int i = threadIdx.x; i < NDEV * D; i += blockDim.x)
        if (acc[i] != 0.f) atomicAdd(&agg[i], acc[i]);
}

// ---------------- dense helpers ----------------
__device__ __forceinline__ void mad16(float* acc, float v, const float* w) {
#pragma unroll
    for (int q = 0; q < 4; q++) {
        float4 ww = ((const float4*)w)[q];
        acc[q * 4 + 0] += v * ww.x;
        acc[q * 4 + 1] += v * ww.y;
        acc[q * 4 + 2] += v * ww.z;
        acc[q * 4 + 3] += v * ww.w;
    }
}

__device__ __forceinline__ void ln_act_store(float* acc, const float* gam, const float* bet,
                                             float* outp) {
    float mu = 0.f;
#pragma unroll
    for (int h = 0; h < 16; h++) mu += acc[h];
    mu *= (1.f / 16.f);
    float var = 0.f;
#pragma unroll
    for (int h = 0; h < 16; h++) { float z = acc[h] - mu; var += z * z; }
    var *= (1.f / 16.f);
    float inv = rsqrtf(var + 1e-5f);
    float4 o[4];
    float* of = (float*)o;
#pragma unroll
    for (int h = 0; h < 16; h++) {
        float y = (acc[h] - mu) * inv * gam[h] + bet[h];
        of[h] = (y > 0.f) ? y : 0.01f * y;
    }
    float4* op = (float4*)outp;
#pragma unroll
    for (int q = 0; q < 4; q++) op[q] = o[q];
}

// ---------------- fused gather + transform + LN : tasks ----------------
__global__ void gather_tasks(const float* __restrict__ x_tasks,
                             const float* __restrict__ x_data,
                             const float* __restrict__ x_dev,
                             const float* __restrict__ W_rel5,
                             const float* __restrict__ W_rel12,
                             const float* __restrict__ b_rel,
                             const float* __restrict__ W_root12,
                             const float* __restrict__ ln_g, const float* __restrict__ ln_b,
                             float* __restrict__ out) {
    __shared__ __align__(16) float W5[80], Wdevt[192], Wto[192], Wfrom[192], Wroot[192];
    __shared__ float bias[16], gam[16], bet[16], sdev[96];
    int t = threadIdx.x;
    if (t < 80) W5[t] = W_rel5[t];
    if (t < 192) {
        Wdevt[t] = W_rel12[2 * 192 + t];
        Wto[t]   = W_rel12[4 * 192 + t];
        Wfrom[t] = W_rel12[5 * 192 + t];
        Wroot[t] = W_root12[t] + W_root12[2 * 192 + t] + W_root12[4 * 192 + t] +
                   W_root12[5 * 192 + t];
    }
    if (t < 16) {
        bias[t] = b_rel[t] + b_rel[3 * 16 + t] + b_rel[6 * 16 + t] + b_rel[7 * 16 + t];
        gam[t] = ln_g[t];
        bet[t] = ln_b[t];
    }
    if (t < 96) sdev[t] = x_dev[t];
    __syncthreads();
    int n = blockIdx.x * blockDim.x + t;
    if (n >= NT) return;

    float acc[16];
#pragma unroll
    for (int h = 0; h < 16; h++) acc[h] = bias[h];

    // data -> tasks (5-dim src)
    {
        int st = g_off[n], de = g_deg[n];
        float a0 = 0.f, a1 = 0.f, a2 = 0.f, a3 = 0.f, a4 = 0.f;
        for (int e = 0; e < de; e++) {
            const float* p = x_data + (size_t)g_srcbuf[st + e] * 5;
            a0 += p[0]; a1 += p[1]; a2 += p[2]; a3 += p[3]; a4 += p[4];
        }
        mad16(acc, a0, &W5[0]);
        mad16(acc, a1, &W5[16]);
        mad16(acc, a2, &W5[32]);
        mad16(acc, a3, &W5[48]);
        mad16(acc, a4, &W5[64]);
    }
    // devices -> tasks (12-dim src, 8 rows in shared)
    {
        int st = g_off[NT + n], de = g_deg[NT + n];
        float a[12];
#pragma unroll
        for (int k = 0; k < 12; k++) a[k] = 0.f;
        for (int e = 0; e < de; e++) {
            int s = g_srcbuf[st + e];
#pragma unroll
            for (int k = 0; k < 12; k++) a[k] += sdev[s * 12 + k];
        }
#pragma unroll
        for (int d = 0; d < 12; d++) mad16(acc, a[d], &Wdevt[d * 16]);
    }
    // tasks -> tasks (to)
    {
        int st = g_off[2 * NT + n], de = g_deg[2 * NT + n];
        float a[12];
#pragma unroll
        for (int k = 0; k < 12; k++) a[k] = 0.f;
        for (int e = 0; e < de; e++) {
            const float4* p = (const float4*)(x_tasks + (size_t)g_srcbuf[st + e] * 12);
            float4 u = p[0], v = p[1], w = p[2];
            a[0] += u.x; a[1] += u.y; a[2]  += u.z; a[3]  += u.w;
            a[4] += v.x; a[5] += v.y; a[6]  += v.z; a[7]  += v.w;
            a[8] += w.x; a[9] += w.y; a[10] += w.z; a[11] += w.w;
        }
#pragma unroll
        for (int d = 0; d < 12; d++) mad16(acc, a[d], &Wto[d * 16]);
    }
    // tasks -> tasks (from)
    {
        int st = g_off[3 * NT + n], de = g_deg[3 * NT + n];
        float a[12];
#pragma unroll
        for (int k = 0; k < 12; k++) a[k] = 0.f;
        for (int e = 0; e < de; e++) {
            const float4* p = (const float4*)(x_tasks + (size_t)g_srcbuf[st + e] * 12);
            float4 u = p[0], v = p[1], w = p[2];
            a[0] += u.x; a[1] += u.y; a[2]  += u.z; a[3]  += u.w;
            a[4] += v.x; a[5] += v.y; a[6]  += v.z; a[7]  += v.w;
            a[8] += w.x; a[9] += w.y; a[10] += w.z; a[11] += w.w;
        }
#pragma unroll
        for (int d = 0; d < 12; d++) mad16(acc, a[d], &Wfrom[d * 16]);
    }
    // root
    {
        const float4* p = (const float4*)(x_tasks + (size_t)n * 12);
        float4 u = p[0], v = p[1], w = p[2];
        float xf[12] = {u.x, u.y, u.z, u.w, v.x, v.y, v.z, v.w, w.x, w.y, w.z, w.w};
#pragma unroll
        for (int d = 0; d < 12; d++) mad16(acc, xf[d], &Wroot[d * 16]);
    }
    ln_act_store(acc, gam, bet, out + (size_t)n * 16);
}

// ---------------- fused gather + transform + LN : data ----------------
__global__ void gather_data(const float* __restrict__ x_tasks,
                            const float* __restrict__ x_data,
                            const float* __restrict__ x_dev,
                            const float* __restrict__ W_rel12,
                            const float* __restrict__ b_rel,
                            const float* __restrict__ W_root5,
                            const float* __restrict__ ln_g, const float* __restrict__ ln_b,
                            float* __restrict__ out) {
    __shared__ __align__(16) float Wtd[192], Wdevd[192], Wroot[80];
    __shared__ float bias[16], gam[16], bet[16], sdev[96];
    int t = threadIdx.x;
    if (t < 192) { Wtd[t] = W_rel12[t]; Wdevd[t] = W_rel12[3 * 192 + t]; }
    if (t < 80)  Wroot[t] = W_root5[t] + W_root5[80 + t];
    if (t < 16) {
        bias[t] = b_rel[16 + t] + b_rel[5 * 16 + t];
        gam[t] = ln_g[16 + t];
        bet[t] = ln_b[16 + t];
    }
    if (t < 96) sdev[t] = x_dev[t];
    __syncthreads();
    int n = blockIdx.x * blockDim.x + t;
    if (n >= ND) return;

    float acc[16];
#pragma unroll
    for (int h = 0; h < 16; h++) acc[h] = bias[h];

    // tasks -> data
    {
        int st = g_off[4 * NT + n], de = g_deg[4 * NT + n];
        float a[12];
#pragma unroll
        for (int k = 0; k < 12; k++) a[k] = 0.f;
        for (int e = 0; e < de; e++) {
            const float4* p = (const float4*)(x_tasks + (size_t)g_srcbuf[st + e] * 12);
            float4 u = p[0], v = p[1], w = p[2];
            a[0] += u.x; a[1] += u.y; a[2]  += u.z; a[3]  += u.w;
            a[4] += v.x; a[5] += v.y; a[6]  += v.z; a[7]  += v.w;
            a[8] += w.x; a[9] += w.y; a[10] += w.z; a[11] += w.w;
        }
#pragma unroll
        for (int d = 0; d < 12; d++) mad16(acc, a[d], &Wtd[d * 16]);
    }
    // devices -> data
    {
        int st = g_off[4 * NT + ND + n], de = g_deg[4 * NT + ND + n];
        float a[12];
#pragma unroll
        for (int k = 0; k < 12; k++) a[k] = 0.f;
        for (int e = 0; e < de; e++) {
            int s = g_srcbuf[st + e];
#pragma unroll
            for (int k = 0; k < 12; k++) a[k] += sdev[s * 12 + k];
        }
#pragma unroll
        for (int d = 0; d < 12; d++) mad16(acc, a[d], &Wdevd[d * 16]);
    }
    // root (5-dim)
    {
        const float* xd = x_data + (size_t)n * 5;
#pragma unroll
        for (int d = 0; d < 5; d++) mad16(acc, xd[d], &Wroot[d * 16]);
    }
    ln_act_store(acc, gam, bet, out + (size_t)n * 16);
}

// ---------------- devices node pass (8 nodes) ----------------
__global__ void dev_node(const float* __restrict__ x_dev,
                         const float* __restrict__ W_rel5, const float* __restrict__ W_rel12,
                         const float* __restrict__ b_rel, const float* __restrict__ W_root12,
                         const float* __restrict__ ln_g, const float* __restrict__ ln_b,
                         float* __restrict__ out) {
    int n = threadIdx.x;
    if (n >= NDEV) return;
    float acc[16];
#pragma unroll
    for (int h = 0; h < 16; h++) acc[h] = b_rel[2 * 16 + h] + b_rel[4 * 16 + h];
    for (int d = 0; d < 12; d++) {
        float v = g_agg_tdev[n * 12 + d];
#pragma unroll
        for (int h = 0; h < 16; h++) acc[h] += v * W_rel12[1 * 192 + d * 16 + h];
    }
    for (int d = 0; d < 5; d++) {
        float v = g_agg_ddev[n * 5 + d];
#pragma unroll
        for (int h = 0; h < 16; h++) acc[h] += v * W_rel5[80 + d * 16 + h];
    }
    for (int d = 0; d < 12; d++) {
        float v = x_dev[n * 12 + d];
#pragma unroll
        for (int h = 0; h < 16; h++)
            acc[h] += v * (W_root12[1 * 192 + d * 16 + h] + W_root12[3 * 192 + d * 16 + h]);
    }
    float gam[16], bet[16];
#pragma unroll
    for (int h = 0; h < 16; h++) { gam[h] = ln_g[2 * 16 + h]; bet[h] = ln_b[2 * 16 + h]; }
    ln_act_store(acc, gam, bet, out + (size_t)n * 16);
}

// ---------------- launch ----------------
extern "C" void kernel_launch(void* const* d_in, const int* in_sizes, int n_in,
                              void* d_out, int out_size) {
    const float* x_tasks = (const float*)d_in[0];
    const float* x_data  = (const float*)d_in[1];
    const float* x_dev   = (const float*)d_in[2];
    const int* ei_dt   = (const int*)d_in[3];   // data  -> tasks
    const int* ei_td   = (const int*)d_in[4];   // tasks -> data
    const int* ei_tdev = (const int*)d_in[5];   // tasks -> devices
    const int* ei_devt = (const int*)d_in[6];   // devices -> tasks
    const int* ei_ddev = (const int*)d_in[7];   // data  -> devices
    const int* ei_devd = (const int*)d_in[8];   // devices -> data
    const int* ei_tto  = (const int*)d_in[9];   // tasks -> tasks (to)
    const int* ei_ttf  = (const int*)d_in[10];  // tasks -> tasks (from)
    const float* W_rel5   = (const float*)d_in[11];
    const float* W_rel12  = (const float*)d_in[12];
    const float* b_rel    = (const float*)d_in[13];
    const float* W_root5  = (const float*)d_in[14];
    const float* W_root12 = (const float*)d_in[15];
    const float* ln_g     = (const float*)d_in[16];
    const float* ln_b     = (const float*)d_in[17];
    float* out = (float*)d_out;

    int E_dt   = in_sizes[3]  / 2;
    int E_td   = in_sizes[4]  / 2;
    int E_tdev = in_sizes[5]  / 2;
    int E_devt = in_sizes[6]  / 2;
    int E_ddev = in_sizes[7]  / 2;
    int E_devd = in_sizes[8]  / 2;
    int E_tto  = in_sizes[9]  / 2;
    int E_ttf  = in_sizes[10] / 2;

    const int TB = 256;
    auto cdiv = [](int a, int b) { return (a + b - 1) / b; };

    zero_deg<<<1024, TB>>>();

    // degree counts (dst histogram per relation segment)
    count_edges<<<cdiv(E_dt,   TB), TB>>>(ei_dt,   E_dt,   0);
    count_edges<<<cdiv(E_devt, TB), TB>>>(ei_devt, E_devt, NT);
    count_edges<<<cdiv(E_tto,  TB), TB>>>(ei_tto,  E_tto,  2 * NT);
    count_edges<<<cdiv(E_ttf,  TB), TB>>>(ei_ttf,  E_ttf,  3 * NT);
    count_edges<<<cdiv(E_td,   TB), TB>>>(ei_td,   E_td,   4 * NT);
    count_edges<<<cdiv(E_devd, TB), TB>>>(ei_devd, E_devd, 4 * NT + ND);

    // one exclusive scan over all segments -> offsets into g_srcbuf
    scan_partial<<<NBLK, 1024>>>();
    scan_bsum<<<1, 1024>>>();
    scan_add<<<NBLK, 1024>>>();

    // fill CSR src lists
    fill_edges<<<cdiv(E_dt,   TB), TB>>>(ei_dt,   E_dt,   0);
    fill_edges<<<cdiv(E_devt, TB), TB>>>(ei_devt, E_devt, NT);
    fill_edges<<<cdiv(E_tto,  TB), TB>>>(ei_tto,  E_tto,  2 * NT);
    fill_edges<<<cdiv(E_ttf,  TB), TB>>>(ei_ttf,  E_ttf,  3 * NT);
    fill_edges<<<cdiv(E_td,   TB), TB>>>(ei_td,   E_td,   4 * NT);
    fill_edges<<<cdiv(E_devd, TB), TB>>>(ei_devd, E_devd, 4 * NT + ND);

    // device-dst relations (tiny, shared-mem accumulate)
    scatter_dev<12><<<256, TB>>>(x_tasks, ei_tdev, E_tdev, 2);
    scatter_dev<5> <<<256, TB>>>(x_data,  ei_ddev, E_ddev, 3);

    // fused gather + transform + LN + activation
    gather_tasks<<<cdiv(NT, TB), TB>>>(x_tasks, x_data, x_dev, W_rel5, W_rel12, b_rel,
                                       W_root12, ln_g, ln_b, out);
    gather_data <<<cdiv(ND, TB), TB>>>(x_tasks, x_data, x_dev, W_rel12, b_rel, W_root5,
                                       ln_g, ln_b, out + (size_t)NT * HID);
    dev_node<<<1, 32>>>(x_dev, W_rel5, W_rel12, b_rel, W_root12,
                        ln_g, ln_b, out + (size_t)(NT + ND) * HID);
}

// round 6
// speedup vs baseline: 1.0839x; 1.0839x over previous
#include <cuda_runtime.h>
#include <cstdint>

#define NT 400000
#define ND 200000
#define NDEV 8

typedef unsigned long long u64;

// ---------------- static scratch ----------------
__device__ __align__(16) float g_acc_tasks[(size_t)NT * 16];  // 25.6 MB
__device__ __align__(16) float g_acc_data [(size_t)ND * 16];  // 12.8 MB
__device__ float g_agg_tdev[NDEV * 12];
__device__ float g_agg_ddev[NDEV * 8];

__device__ __forceinline__ float* acc_sel(int which) {
    return (which == 0) ? g_acc_tasks : g_acc_data;
}

// ---------------- packed f32x2 helpers ----------------
__device__ __forceinline__ u64 pack2(float x, float y) {
    u64 r; asm("mov.b64 %0, {%1,%2};" : "=l"(r) : "f"(x), "f"(y)); return r;
}
__device__ __forceinline__ float2 unpack2(u64 v) {
    float2 r; asm("mov.b64 {%0,%1}, %2;" : "=f"(r.x), "=f"(r.y) : "l"(v)); return r;
}
__device__ __forceinline__ void fma2(u64& d, u64 a, u64 b) {  // d = a*b + d
    asm("fma.rn.f32x2 %0, %1, %2, %0;" : "+l"(d) : "l"(a), "l"(b));
}

__device__ __forceinline__ void red4(float* p, float a, float b, float c, float d) {
    asm volatile("red.global.add.v4.f32 [%0], {%1,%2,%3,%4};"
                 :: "l"(p), "f"(a), "f"(b), "f"(c), "f"(d) : "memory");
}

// ---------------- zero ----------------
__global__ void zero_acc() {
    float4 z = make_float4(0.f, 0.f, 0.f, 0.f);
    size_t n1 = (size_t)NT * 16 / 4, n2 = (size_t)ND * 16 / 4;
    size_t i = (size_t)blockIdx.x * blockDim.x + threadIdx.x;
    size_t st = (size_t)gridDim.x * blockDim.x;
    for (size_t j = i; j < n1; j += st) ((float4*)g_acc_tasks)[j] = z;
    for (size_t j = i; j < n2; j += st) ((float4*)g_acc_data)[j] = z;
    if (i < NDEV * 12) g_agg_tdev[i] = 0.f;
    if (i < NDEV * 8)  g_agg_ddev[i] = 0.f;
}

// ---------------- emit 16-float accumulate ----------------
__device__ __forceinline__ void emit16(float* p, const u64* ac) {
    float2 f0 = unpack2(ac[0]), f1 = unpack2(ac[1]), f2 = unpack2(ac[2]), f3 = unpack2(ac[3]);
    float2 f4 = unpack2(ac[4]), f5 = unpack2(ac[5]), f6 = unpack2(ac[6]), f7 = unpack2(ac[7]);
    red4(p,      f0.x, f0.y, f1.x, f1.y);
    red4(p + 4,  f2.x, f2.y, f3.x, f3.y);
    red4(p + 8,  f4.x, f4.y, f5.x, f5.y);
    red4(p + 12, f6.x, f6.y, f7.x, f7.y);
}

// ---------------- transform-first scatter: 12-dim src ----------------
__global__ void xscat12(const float* __restrict__ xsrc, const int* __restrict__ ei, int E,
                        const float* __restrict__ Wg, int which) {
    __shared__ u64 sW[96];   // 12 x 16 packed as 12 x 8 pairs
    int t = threadIdx.x;
    if (t < 96) sW[t] = pack2(Wg[2 * t], Wg[2 * t + 1]);
    __syncthreads();
    int e = blockIdx.x * blockDim.x + t;
    if (e >= E) return;
    int s = ei[e], d = ei[E + e];
    const float4* xr = (const float4*)(xsrc + (size_t)s * 12);
    float4 a = xr[0], b = xr[1], c = xr[2];
    float xf[12] = {a.x, a.y, a.z, a.w, b.x, b.y, b.z, b.w, c.x, c.y, c.z, c.w};
    u64 ac[8];
#pragma unroll
    for (int j = 0; j < 8; j++) ac[j] = 0ull;   // (0.f,0.f)
#pragma unroll
    for (int dd = 0; dd < 12; dd++) {
        u64 vv = pack2(xf[dd], xf[dd]);
#pragma unroll
        for (int j = 0; j < 8; j++) fma2(ac[j], vv, sW[dd * 8 + j]);
    }
    emit16(acc_sel(which) + (size_t)d * 16, ac);
}

// ---------------- transform-first scatter: 5-dim src ----------------
__global__ void xscat5(const float* __restrict__ xsrc, const int* __restrict__ ei, int E,
                       const float* __restrict__ Wg, int which) {
    __shared__ u64 sW[40];
    int t = threadIdx.x;
    if (t < 40) sW[t] = pack2(Wg[2 * t], Wg[2 * t + 1]);
    __syncthreads();
    int e = blockIdx.x * blockDim.x + t;
    if (e >= E) return;
    int s = ei[e], d = ei[E + e];
    const float* xr = xsrc + (size_t)s * 5;
    float xf[5] = {xr[0], xr[1], xr[2], xr[3], xr[4]};
    u64 ac[8];
#pragma unroll
    for (int j = 0; j < 8; j++) ac[j] = 0ull;
#pragma unroll
    for (int dd = 0; dd < 5; dd++) {
        u64 vv = pack2(xf[dd], xf[dd]);
#pragma unroll
        for (int j = 0; j < 8; j++) fma2(ac[j], vv, sW[dd * 8 + j]);
    }
    emit16(acc_sel(which) + (size_t)d * 16, ac);
}

// ---------------- device-source scatter: pre-transform 8 rows into shared ----------------
__global__ void devscat(const float* __restrict__ xdev, const int* __restrict__ ei, int E,
                        const float* __restrict__ Wg, int which) {
    __shared__ __align__(16) float y[NDEV * 16];
    int t = threadIdx.x;
    if (t < NDEV * 16) {
        int n = t >> 4, h = t & 15;
        float s = 0.f;
#pragma unroll
        for (int d = 0; d < 12; d++) s += xdev[n * 12 + d] * Wg[d * 16 + h];
        y[t] = s;
    }
    __syncthreads();
    int e = blockIdx.x * blockDim.x + t;
    if (e >= E) return;
    int s = ei[e], d = ei[E + e];
    const float* ys = y + s * 16;
    float* p = acc_sel(which) + (size_t)d * 16;
    red4(p,      ys[0],  ys[1],  ys[2],  ys[3]);
    red4(p + 4,  ys[4],  ys[5],  ys[6],  ys[7]);
    red4(p + 8,  ys[8],  ys[9],  ys[10], ys[11]);
    red4(p + 12, ys[12], ys[13], ys[14], ys[15]);
}

// ---------------- device-dst relations: shared-mem scatter (tiny) ----------------
template <int D>
__global__ void scatter_dev(const float* __restrict__ xsrc, const int* __restrict__ ei,
                            int E, int which) {
    __shared__ float acc[NDEV * D];
    for (int i = threadIdx.x; i < NDEV * D; i += blockDim.x) acc[i] = 0.f;
    __syncthreads();
    for (int e = blockIdx.x * blockDim.x + threadIdx.x; e < E;
         e += gridDim.x * blockDim.x) {
        int s = ei[e];
        int d = ei[E + e];
        const float* xr = xsrc + (size_t)s * D;
#pragma unroll
        for (int k = 0; k < D; k++) atomicAdd(&acc[d * D + k], xr[k]);
    }
    __syncthreads();
    float* agg = (which == 2) ? g_agg_tdev : g_agg_ddev;
    for (int i = threadIdx.x; i < NDEV * D; i += blockDim.x)
        if (acc[i] != 0.f) atomicAdd(&agg[i], acc[i]);
}

// ---------------- LN + leaky relu + store ----------------
__device__ __forceinline__ void ln_act_store(float* a, const float* gam, const float* bet,
                                             float* outp) {
    float mu = 0.f;
#pragma unroll
    for (int h = 0; h < 16; h++) mu += a[h];
    mu *= (1.f / 16.f);
    float var = 0.f;
#pragma unroll
    for (int h = 0; h < 16; h++) { float z = a[h] - mu; var += z * z; }
    var *= (1.f / 16.f);
    float inv = rsqrtf(var + 1e-5f);
    float4 o[4];
    float* of = (float*)o;
#pragma unroll
    for (int h = 0; h < 16; h++) {
        float y = (a[h] - mu) * inv * gam[h] + bet[h];
        of[h] = (y > 0.f) ? y : 0.01f * y;
    }
    float4* op = (float4*)outp;
#pragma unroll
    for (int q = 0; q < 4; q++) op[q] = o[q];
}

// ---------------- tasks node pass ----------------
__global__ void tasks_node(const float* __restrict__ x_tasks,
                           const float* __restrict__ b_rel,
                           const float* __restrict__ W_root12,
                           const float* __restrict__ ln_g, const float* __restrict__ ln_b,
                           float* __restrict__ out) {
    __shared__ u64 sroot[96];
    __shared__ float bias[16], gam[16], bet[16];
    int t = threadIdx.x;
    if (t < 96) {
        float w0 = W_root12[2 * t]     + W_root12[2 * 192 + 2 * t] +
                   W_root12[4 * 192 + 2 * t] + W_root12[5 * 192 + 2 * t];
        float w1 = W_root12[2 * t + 1] + W_root12[2 * 192 + 2 * t + 1] +
                   W_root12[4 * 192 + 2 * t + 1] + W_root12[5 * 192 + 2 * t + 1];
        sroot[t] = pack2(w0, w1);
    }
    if (t < 16) {
        bias[t] = b_rel[t] + b_rel[3 * 16 + t] + b_rel[6 * 16 + t] + b_rel[7 * 16 + t];
        gam[t] = ln_g[t];
        bet[t] = ln_b[t];
    }
    __syncthreads();
    int n = blockIdx.x * blockDim.x + t;
    if (n >= NT) return;

    const u64* rp = (const u64*)(g_acc_tasks + (size_t)n * 16);
    u64 ac[8];
#pragma unroll
    for (int j = 0; j < 8; j++) ac[j] = rp[j];

    const float4* xr = (const float4*)(x_tasks + (size_t)n * 12);
    float4 a = xr[0], b = xr[1], c = xr[2];
    float xf[12] = {a.x, a.y, a.z, a.w, b.x, b.y, b.z, b.w, c.x, c.y, c.z, c.w};
#pragma unroll
    for (int dd = 0; dd < 12; dd++) {
        u64 vv = pack2(xf[dd], xf[dd]);
#pragma unroll
        for (int j = 0; j < 8; j++) fma2(ac[j], vv, sroot[dd * 8 + j]);
    }
    float av[16];
#pragma unroll
    for (int j = 0; j < 8; j++) {
        float2 f = unpack2(ac[j]);
        av[2 * j] = f.x + bias[2 * j];
        av[2 * j + 1] = f.y + bias[2 * j + 1];
    }
    ln_act_store(av, gam, bet, out + (size_t)n * 16);
}

// ---------------- data node pass ----------------
__global__ void data_node(const float* __restrict__ x_data,
                          const float* __restrict__ b_rel,
                          const float* __restrict__ W_root5,
                          const float* __restrict__ ln_g, const float* __restrict__ ln_b,
                          float* __restrict__ out) {
    __shared__ u64 sroot[40];
    __shared__ float bias[16], gam[16], bet[16];
    int t = threadIdx.x;
    if (t < 40) {
        float w0 = W_root5[2 * t]     + W_root5[80 + 2 * t];
        float w1 = W_root5[2 * t + 1] + W_root5[80 + 2 * t + 1];
        sroot[t] = pack2(w0, w1);
    }
    if (t < 16) {
        bias[t] = b_rel[16 + t] + b_rel[5 * 16 + t];
        gam[t] = ln_g[16 + t];
        bet[t] = ln_b[16 + t];
    }
    __syncthreads();
    int n = blockIdx.x * blockDim.x + t;
    if (n >= ND) return;

    const u64* rp = (const u64*)(g_acc_data + (size_t)n * 16);
    u64 ac[8];
#pragma unroll
    for (int j = 0; j < 8; j++) ac[j] = rp[j];

    const float* xd = x_data + (size_t)n * 5;
    float xf[5] = {xd[0], xd[1], xd[2], xd[3], xd[4]};
#pragma unroll
    for (int dd = 0; dd < 5; dd++) {
        u64 vv = pack2(xf[dd], xf[dd]);
#pragma unroll
        for (int j = 0; j < 8; j++) fma2(ac[j], vv, sroot[dd * 8 + j]);
    }
    float av[16];
#pragma unroll
    for (int j = 0; j < 8; j++) {
        float2 f = unpack2(ac[j]);
        av[2 * j] = f.x + bias[2 * j];
        av[2 * j + 1] = f.y + bias[2 * j + 1];
    }
    ln_act_store(av, gam, bet, out + (size_t)n * 16);
}

// ---------------- devices node pass (8 nodes) ----------------
__global__ void dev_node(const float* __restrict__ x_dev,
                         const float* __restrict__ W_rel5, const float* __restrict__ W_rel12,
                         const float* __restrict__ b_rel, const float* __restrict__ W_root12,
                         const float* __restrict__ ln_g, const float* __restrict__ ln_b,
                         float* __restrict__ out) {
    int n = threadIdx.x;
    if (n >= NDEV) return;
    float acc[16];
#pragma unroll
    for (int h = 0; h < 16; h++) acc[h] = b_rel[2 * 16 + h] + b_rel[4 * 16 + h];
    for (int d = 0; d < 12; d++) {
        float v = g_agg_tdev[n * 12 + d];
#pragma unroll
        for (int h = 0; h < 16; h++) acc[h] += v * W_rel12[1 * 192 + d * 16 + h];
    }
    for (int d = 0; d < 5; d++) {
        float v = g_agg_ddev[n * 5 + d];
#pragma unroll
        for (int h = 0; h < 16; h++) acc[h] += v * W_rel5[80 + d * 16 + h];
    }
    for (int d = 0; d < 12; d++) {
        float v = x_dev[n * 12 + d];
#pragma unroll
        for (int h = 0; h < 16; h++)
            acc[h] += v * (W_root12[1 * 192 + d * 16 + h] + W_root12[3 * 192 + d * 16 + h]);
    }
    float gam[16], bet[16];
#pragma unroll
    for (int h = 0; h < 16; h++) { gam[h] = ln_g[2 * 16 + h]; bet[h] = ln_b[2 * 16 + h]; }
    ln_act_store(acc, gam, bet, out + (size_t)n * 16);
}

// ---------------- launch ----------------
extern "C" void kernel_launch(void* const* d_in, const int* in_sizes, int n_in,
                              void* d_out, int out_size) {
    const float* x_tasks = (const float*)d_in[0];
    const float* x_data  = (const float*)d_in[1];
    const float* x_dev   = (const float*)d_in[2];
    const int* ei_dt   = (const int*)d_in[3];   // data  -> tasks
    const int* ei_td   = (const int*)d_in[4];   // tasks -> data
    const int* ei_tdev = (const int*)d_in[5];   // tasks -> devices
    const int* ei_devt = (const int*)d_in[6];   // devices -> tasks
    const int* ei_ddev = (const int*)d_in[7];   // data  -> devices
    const int* ei_devd = (const int*)d_in[8];   // devices -> data
    const int* ei_tto  = (const int*)d_in[9];   // tasks -> tasks (to)
    const int* ei_ttf  = (const int*)d_in[10];  // tasks -> tasks (from)
    const float* W_rel5   = (const float*)d_in[11];
    const float* W_rel12  = (const float*)d_in[12];
    const float* b_rel    = (const float*)d_in[13];
    const float* W_root5  = (const float*)d_in[14];
    const float* W_root12 = (const float*)d_in[15];
    const float* ln_g     = (const float*)d_in[16];
    const float* ln_b     = (const float*)d_in[17];
    float* out = (float*)d_out;

    int E_dt   = in_sizes[3]  / 2;
    int E_td   = in_sizes[4]  / 2;
    int E_tdev = in_sizes[5]  / 2;
    int E_devt = in_sizes[6]  / 2;
    int E_ddev = in_sizes[7]  / 2;
    int E_devd = in_sizes[8]  / 2;
    int E_tto  = in_sizes[9]  / 2;
    int E_ttf  = in_sizes[10] / 2;

    const int TB = 256;
    auto cdiv = [](int a, int b) { return (a + b - 1) / b; };

    zero_acc<<<1024, TB>>>();

    // transform-first scatters into 16-float accumulators (0 = tasks, 1 = data)
    xscat5 <<<cdiv(E_dt,  TB), TB>>>(x_data,  ei_dt,  E_dt,  W_rel5,              0);
    devscat<<<cdiv(E_devt, TB), TB>>>(x_dev,  ei_devt, E_devt, W_rel12 + 2 * 192, 0);
    xscat12<<<cdiv(E_tto, TB), TB>>>(x_tasks, ei_tto, E_tto, W_rel12 + 4 * 192,   0);
    xscat12<<<cdiv(E_ttf, TB), TB>>>(x_tasks, ei_ttf, E_ttf, W_rel12 + 5 * 192,   0);
    xscat12<<<cdiv(E_td,  TB), TB>>>(x_tasks, ei_td,  E_td,  W_rel12,             1);
    devscat<<<cdiv(E_devd, TB), TB>>>(x_dev,  ei_devd, E_devd, W_rel12 + 3 * 192, 1);

    // device-dst relations (tiny, shared-mem accumulate)
    scatter_dev<12><<<256, TB>>>(x_tasks, ei_tdev, E_tdev, 2);
    scatter_dev<5> <<<256, TB>>>(x_data,  ei_ddev, E_ddev, 3);

    // node passes
    tasks_node<<<cdiv(NT, TB), TB>>>(x_tasks, b_rel, W_root12, ln_g, ln_b, out);
    data_node <<<cdiv(ND, TB), TB>>>(x_data, b_rel, W_root5, ln_g, ln_b,
                                     out + (size_t)NT * 16);
    dev_node<<<1, 32>>>(x_dev, W_rel5, W_rel12, b_rel, W_root12,
                        ln_g, ln_b, out + (size_t)(NT + ND) * 16);
}

// round 7
// speedup vs baseline: 1.7036x; 1.5717x over previous
#include <cuda_runtime.h>
#include <cstdint>

#define NT 400000
#define ND 200000

typedef unsigned long long u64;

// ---------------- static scratch (referenced ONLY from device code) ----------------
__device__ __align__(16) float g_dt [(size_t)NT * 8];    // data->tasks raw sums (5 used, pad 8)  12.8MB
__device__ __align__(16) float g_to [(size_t)NT * 12];   // tt_to raw sums                        19.2MB
__device__ __align__(16) float g_fr [(size_t)NT * 12];   // tt_from raw sums                      19.2MB
__device__ __align__(16) float g_td [(size_t)ND * 12];   // tasks->data raw sums                   9.6MB
__device__ __align__(16) u64   g_cdevt[NT];              // devices->tasks packed 8x8bit counts    3.2MB
__device__ __align__(16) u64   g_cdevd[ND];              // devices->data packed counts            1.6MB
__device__ float g_tdev[8 * 12];                         // tasks->devices agg
__device__ float g_ddev[8 * 8];                          // data->devices agg (5 used, stride 8)
__device__ __align__(16) float g_xd8[(size_t)ND * 8];    // x_data padded to stride 8              6.4MB

// ---------------- helpers ----------------
__device__ __forceinline__ u64 pack2(float x, float y) {
    u64 r; asm("mov.b64 %0, {%1,%2};" : "=l"(r) : "f"(x), "f"(y)); return r;
}
__device__ __forceinline__ float2 unpack2(u64 v) {
    float2 r; asm("mov.b64 {%0,%1}, %2;" : "=f"(r.x), "=f"(r.y) : "l"(v)); return r;
}
__device__ __forceinline__ void fma2(u64& d, u64 a, u64 b) {  // d = a*b + d (packed f32x2)
    asm("fma.rn.f32x2 %0, %1, %2, %0;" : "+l"(d) : "l"(a), "l"(b));
}
__device__ __forceinline__ void red4(float* p, float a, float b, float c, float d) {
    asm volatile("red.global.add.v4.f32 [%0], {%1,%2,%3,%4};"
                 :: "l"(p), "f"(a), "f"(b), "f"(c), "f"(d) : "memory");
}
__device__ __forceinline__ void red1(float* p, float a) {
    asm volatile("red.global.add.f32 [%0], %1;" :: "l"(p), "f"(a) : "memory");
}
__device__ __forceinline__ void redu64(u64* p, u64 v) {
    asm volatile("red.global.add.u64 [%0], %1;" :: "l"(p), "l"(v) : "memory");
}

// ---------------- prep: zero scratch + pad x_data ----------------
__global__ void prep(const float* __restrict__ xd) {
    size_t i  = (size_t)blockIdx.x * blockDim.x + threadIdx.x;
    size_t st = (size_t)gridDim.x * blockDim.x;
    float4 z = make_float4(0.f, 0.f, 0.f, 0.f);
    for (size_t j = i; j < (size_t)NT * 2; j += st) ((float4*)g_dt)[j] = z;
    for (size_t j = i; j < (size_t)NT * 3; j += st) ((float4*)g_to)[j] = z;
    for (size_t j = i; j < (size_t)NT * 3; j += st) ((float4*)g_fr)[j] = z;
    for (size_t j = i; j < (size_t)ND * 3; j += st) ((float4*)g_td)[j] = z;
    for (size_t j = i; j < (size_t)NT / 2; j += st) ((float4*)g_cdevt)[j] = z;
    for (size_t j = i; j < (size_t)ND / 2; j += st) ((float4*)g_cdevd)[j] = z;
    if (i < 96) g_tdev[i] = 0.f;
    if (i < 64) g_ddev[i] = 0.f;
    for (size_t j = i; j < (size_t)ND; j += st) {
        const float* r = xd + j * 5;
        float4* o = (float4*)(g_xd8 + j * 8);
        o[0] = make_float4(r[0], r[1], r[2], r[3]);
        o[1] = make_float4(r[4], 0.f, 0.f, 0.f);
    }
}

// ---------------- fused scatter: all 8 relations, one launch ----------------
__global__ void fused_scatter(
    const float* __restrict__ xt,
    const int* __restrict__ e_dt,   int E_dt,
    const int* __restrict__ e_to,   int E_to,
    const int* __restrict__ e_fr,   int E_fr,
    const int* __restrict__ e_td,   int E_td,
    const int* __restrict__ e_devt, int E_devt,
    const int* __restrict__ e_devd, int E_devd,
    const int* __restrict__ e_tdev, int E_tdev,
    const int* __restrict__ e_ddev, int E_ddev,
    int b0, int b1, int b2, int b3, int b4, int b5, int b6) {
    int b = blockIdx.x, t = threadIdx.x;

    if (b < b0) {                       // data -> tasks (5-dim, padded src)
        int e = b * 256 + t;
        if (e >= E_dt) return;
        int s = e_dt[e], d = e_dt[E_dt + e];
        const float4* xr = (const float4*)(g_xd8 + (size_t)s * 8);
        float4 A = xr[0], B = xr[1];
        float* p = g_dt + (size_t)d * 8;
        red4(p, A.x, A.y, A.z, A.w);
        red1(p + 4, B.x);
    } else if (b < b1) {                // tt_to
        int e = (b - b0) * 256 + t;
        if (e >= E_to) return;
        int s = e_to[e], d = e_to[E_to + e];
        const float4* xr = (const float4*)(xt + (size_t)s * 12);
        float4 A = xr[0], B = xr[1], C = xr[2];
        float* p = g_to + (size_t)d * 12;
        red4(p, A.x, A.y, A.z, A.w);
        red4(p + 4, B.x, B.y, B.z, B.w);
        red4(p + 8, C.x, C.y, C.z, C.w);
    } else if (b < b2) {                // tt_from
        int e = (b - b1) * 256 + t;
        if (e >= E_fr) return;
        int s = e_fr[e], d = e_fr[E_fr + e];
        const float4* xr = (const float4*)(xt + (size_t)s * 12);
        float4 A = xr[0], B = xr[1], C = xr[2];
        float* p = g_fr + (size_t)d * 12;
        red4(p, A.x, A.y, A.z, A.w);
        red4(p + 4, B.x, B.y, B.z, B.w);
        red4(p + 8, C.x, C.y, C.z, C.w);
    } else if (b < b3) {                // tasks -> data
        int e = (b - b2) * 256 + t;
        if (e >= E_td) return;
        int s = e_td[e], d = e_td[E_td + e];
        const float4* xr = (const float4*)(xt + (size_t)s * 12);
        float4 A = xr[0], B = xr[1], C = xr[2];
        float* p = g_td + (size_t)d * 12;
        red4(p, A.x, A.y, A.z, A.w);
        red4(p + 4, B.x, B.y, B.z, B.w);
        red4(p + 8, C.x, C.y, C.z, C.w);
    } else if (b < b4) {                // devices -> tasks : packed count
        int e = (b - b3) * 256 + t;
        if (e >= E_devt) return;
        int s = e_devt[e], d = e_devt[E_devt + e];
        redu64(&g_cdevt[d], 1ull << (s * 8));
    } else if (b < b5) {                // devices -> data : packed count
        int e = (b - b4) * 256 + t;
        if (e >= E_devd) return;
        int s = e_devd[e], d = e_devd[E_devd + e];
        redu64(&g_cdevd[d], 1ull << (s * 8));
    } else if (b < b6) {                // tasks -> devices (dst in [0,8))
        __shared__ float acc[96];
        if (t < 96) acc[t] = 0.f;
        __syncthreads();
        int e = (b - b5) * 256 + t;
        if (e < E_tdev) {
            int s = e_tdev[e], d = e_tdev[E_tdev + e];
            const float4* xr = (const float4*)(xt + (size_t)s * 12);
            float4 A = xr[0], B = xr[1], C = xr[2];
            float* a = acc + d * 12;
            atomicAdd(a + 0, A.x);  atomicAdd(a + 1, A.y);
            atomicAdd(a + 2, A.z);  atomicAdd(a + 3, A.w);
            atomicAdd(a + 4, B.x);  atomicAdd(a + 5, B.y);
            atomicAdd(a + 6, B.z);  atomicAdd(a + 7, B.w);
            atomicAdd(a + 8, C.x);  atomicAdd(a + 9, C.y);
            atomicAdd(a + 10, C.z); atomicAdd(a + 11, C.w);
        }
        __syncthreads();
        if (t < 96 && acc[t] != 0.f) red1(&g_tdev[t], acc[t]);
    } else {                            // data -> devices (5-dim)
        __shared__ float acc[64];
        if (t < 64) acc[t] = 0.f;
        __syncthreads();
        int e = (b - b6) * 256 + t;
        if (e < E_ddev) {
            int s = e_ddev[e], d = e_ddev[E_ddev + e];
            const float4* xr = (const float4*)(g_xd8 + (size_t)s * 8);
            float4 A = xr[0], B = xr[1];
            float* a = acc + d * 8;
            atomicAdd(a + 0, A.x); atomicAdd(a + 1, A.y);
            atomicAdd(a + 2, A.z); atomicAdd(a + 3, A.w);
            atomicAdd(a + 4, B.x);
        }
        __syncthreads();
        if (t < 64 && acc[t] != 0.f) red1(&g_ddev[t], acc[t]);
    }
}

// ---------------- LN + leaky relu + store ----------------
__device__ __forceinline__ void ln_act_store(float* a, const float* gam, const float* bet,
                                             float* outp) {
    float mu = 0.f;
#pragma unroll
    for (int h = 0; h < 16; h++) mu += a[h];
    mu *= (1.f / 16.f);
    float var = 0.f;
#pragma unroll
    for (int h = 0; h < 16; h++) { float z = a[h] - mu; var += z * z; }
    var *= (1.f / 16.f);
    float inv = rsqrtf(var + 1e-5f);
    float4 o[4];
    float* of = (float*)o;
#pragma unroll
    for (int h = 0; h < 16; h++) {
        float y = (a[h] - mu) * inv * gam[h] + bet[h];
        of[h] = (y > 0.f) ? y : 0.01f * y;
    }
    float4* op = (float4*)outp;
#pragma unroll
    for (int q = 0; q < 4; q++) op[q] = o[q];
}

#define NBT ((NT + 255) / 256)   // 1563
#define NBD ((ND + 255) / 256)   // 782

// ---------------- fused node pass: tasks | data | devices ----------------
__global__ void fused_node(const float* __restrict__ xt,
                           const float* __restrict__ xv,
                           const float* __restrict__ W_rel5,
                           const float* __restrict__ W_rel12,
                           const float* __restrict__ b_rel,
                           const float* __restrict__ W_root5,
                           const float* __restrict__ W_root12,
                           const float* __restrict__ ln_g,
                           const float* __restrict__ ln_b,
                           float* __restrict__ out) {
    __shared__ __align__(16) u64 sm[392];
    __shared__ float smf[48];
    int bb = blockIdx.x, t = threadIdx.x;

    if (bb < NBT) {
        // ---- tasks ----
        u64* sW5  = sm;          // 40  : W_rel5[0]
        u64* sYd  = sm + 40;     // 64  : y_devt = x_dev @ W_rel12[2]  (8 x 16)
        u64* sWto = sm + 104;    // 96  : W_rel12[4]
        u64* sWfr = sm + 200;    // 96  : W_rel12[5]
        u64* sWrt = sm + 296;    // 96  : sum of W_root12[0,2,4,5]
        if (t < 40) sW5[t] = pack2(W_rel5[2 * t], W_rel5[2 * t + 1]);
        if (t < 96) {
            sWto[t] = pack2(W_rel12[4 * 192 + 2 * t], W_rel12[4 * 192 + 2 * t + 1]);
            sWfr[t] = pack2(W_rel12[5 * 192 + 2 * t], W_rel12[5 * 192 + 2 * t + 1]);
            float w0 = W_root12[2 * t] + W_root12[2 * 192 + 2 * t] +
                       W_root12[4 * 192 + 2 * t] + W_root12[5 * 192 + 2 * t];
            float w1 = W_root12[2 * t + 1] + W_root12[2 * 192 + 2 * t + 1] +
                       W_root12[4 * 192 + 2 * t + 1] + W_root12[5 * 192 + 2 * t + 1];
            sWrt[t] = pack2(w0, w1);
        }
        if (t < 64) {
            int n = t >> 3, h0 = (t & 7) * 2;
            float y0 = 0.f, y1 = 0.f;
#pragma unroll
            for (int d = 0; d < 12; d++) {
                float xvv = xv[n * 12 + d];
                y0 += xvv * W_rel12[2 * 192 + d * 16 + h0];
                y1 += xvv * W_rel12[2 * 192 + d * 16 + h0 + 1];
            }
            sYd[t] = pack2(y0, y1);
        }
        if (t < 16) {
            smf[t]      = b_rel[t] + b_rel[3 * 16 + t] + b_rel[6 * 16 + t] + b_rel[7 * 16 + t];
            smf[16 + t] = ln_g[t];
            smf[32 + t] = ln_b[t];
        }
        __syncthreads();
        int n = bb * 256 + t;
        if (n >= NT) return;

        u64 ac[8];
#pragma unroll
        for (int j = 0; j < 8; j++) ac[j] = pack2(smf[2 * j], smf[2 * j + 1]);

        // dt (5-dim raw sums)
        {
            const float4* rp = (const float4*)(g_dt + (size_t)n * 8);
            float4 A = rp[0], B = rp[1];
            float a[5] = {A.x, A.y, A.z, A.w, B.x};
#pragma unroll
            for (int d = 0; d < 5; d++) {
                u64 vv = pack2(a[d], a[d]);
#pragma unroll
                for (int j = 0; j < 8; j++) fma2(ac[j], vv, sW5[d * 8 + j]);
            }
        }
        // devt counts
        {
            u64 c = g_cdevt[n];
            if (c) {
#pragma unroll
                for (int s = 0; s < 8; s++) {
                    float cs = (float)((c >> (8 * s)) & 0xFF);
                    if (cs != 0.f) {
                        u64 vv = pack2(cs, cs);
#pragma unroll
                        for (int j = 0; j < 8; j++) fma2(ac[j], vv, sYd[s * 8 + j]);
                    }
                }
            }
        }
        // tt_to raw sums
        {
            const float4* rp = (const float4*)(g_to + (size_t)n * 12);
            float4 A = rp[0], B = rp[1], C = rp[2];
            float a[12] = {A.x, A.y, A.z, A.w, B.x, B.y, B.z, B.w, C.x, C.y, C.z, C.w};
#pragma unroll
            for (int d = 0; d < 12; d++) {
                u64 vv = pack2(a[d], a[d]);
#pragma unroll
                for (int j = 0; j < 8; j++) fma2(ac[j], vv, sWto[d * 8 + j]);
            }
        }
        // tt_from raw sums
        {
            const float4* rp = (const float4*)(g_fr + (size_t)n * 12);
            float4 A = rp[0], B = rp[1], C = rp[2];
            float a[12] = {A.x, A.y, A.z, A.w, B.x, B.y, B.z, B.w, C.x, C.y, C.z, C.w};
#pragma unroll
            for (int d = 0; d < 12; d++) {
                u64 vv = pack2(a[d], a[d]);
#pragma unroll
                for (int j = 0; j < 8; j++) fma2(ac[j], vv, sWfr[d * 8 + j]);
            }
        }
        // root
        {
            const float4* rp = (const float4*)(xt + (size_t)n * 12);
            float4 A = rp[0], B = rp[1], C = rp[2];
            float a[12] = {A.x, A.y, A.z, A.w, B.x, B.y, B.z, B.w, C.x, C.y, C.z, C.w};
#pragma unroll
            for (int d = 0; d < 12; d++) {
                u64 vv = pack2(a[d], a[d]);
#pragma unroll
                for (int j = 0; j < 8; j++) fma2(ac[j], vv, sWrt[d * 8 + j]);
            }
        }
        float av[16];
#pragma unroll
        for (int j = 0; j < 8; j++) {
            float2 f = unpack2(ac[j]);
            av[2 * j] = f.x; av[2 * j + 1] = f.y;
        }
        ln_act_store(av, smf + 16, smf + 32, out + (size_t)n * 16);

    } else if (bb < NBT + NBD) {
        // ---- data ----
        u64* sWtd  = sm;         // 96 : W_rel12[0]
        u64* sYdd  = sm + 96;    // 64 : y_devd = x_dev @ W_rel12[3]
        u64* sWrt5 = sm + 160;   // 40 : W_root5[0] + W_root5[1]
        if (t < 96) sWtd[t] = pack2(W_rel12[2 * t], W_rel12[2 * t + 1]);
        if (t < 64) {
            int n = t >> 3, h0 = (t & 7) * 2;
            float y0 = 0.f, y1 = 0.f;
#pragma unroll
            for (int d = 0; d < 12; d++) {
                float xvv = xv[n * 12 + d];
                y0 += xvv * W_rel12[3 * 192 + d * 16 + h0];
                y1 += xvv * W_rel12[3 * 192 + d * 16 + h0 + 1];
            }
            sYdd[t] = pack2(y0, y1);
        }
        if (t < 40) {
            float w0 = W_root5[2 * t]     + W_root5[80 + 2 * t];
            float w1 = W_root5[2 * t + 1] + W_root5[80 + 2 * t + 1];
            sWrt5[t] = pack2(w0, w1);
        }
        if (t < 16) {
            smf[t]      = b_rel[16 + t] + b_rel[5 * 16 + t];
            smf[16 + t] = ln_g[16 + t];
            smf[32 + t] = ln_b[16 + t];
        }
        __syncthreads();
        int n = (bb - NBT) * 256 + t;
        if (n >= ND) return;

        u64 ac[8];
#pragma unroll
        for (int j = 0; j < 8; j++) ac[j] = pack2(smf[2 * j], smf[2 * j + 1]);

        // td raw sums
        {
            const float4* rp = (const float4*)(g_td + (size_t)n * 12);
            float4 A = rp[0], B = rp[1], C = rp[2];
            float a[12] = {A.x, A.y, A.z, A.w, B.x, B.y, B.z, B.w, C.x, C.y, C.z, C.w};
#pragma unroll
            for (int d = 0; d < 12; d++) {
                u64 vv = pack2(a[d], a[d]);
#pragma unroll
                for (int j = 0; j < 8; j++) fma2(ac[j], vv, sWtd[d * 8 + j]);
            }
        }
        // devd counts
        {
            u64 c = g_cdevd[n];
            if (c) {
#pragma unroll
                for (int s = 0; s < 8; s++) {
                    float cs = (float)((c >> (8 * s)) & 0xFF);
                    if (cs != 0.f) {
                        u64 vv = pack2(cs, cs);
#pragma unroll
                        for (int j = 0; j < 8; j++) fma2(ac[j], vv, sYdd[s * 8 + j]);
                    }
                }
            }
        }
        // root (5-dim, padded copy)
        {
            const float4* rp = (const float4*)(g_xd8 + (size_t)n * 8);
            float4 A = rp[0], B = rp[1];
            float a[5] = {A.x, A.y, A.z, A.w, B.x};
#pragma unroll
            for (int d = 0; d < 5; d++) {
                u64 vv = pack2(a[d], a[d]);
#pragma unroll
                for (int j = 0; j < 8; j++) fma2(ac[j], vv, sWrt5[d * 8 + j]);
            }
        }
        float av[16];
#pragma unroll
        for (int j = 0; j < 8; j++) {
            float2 f = unpack2(ac[j]);
            av[2 * j] = f.x; av[2 * j + 1] = f.y;
        }
        ln_act_store(av, smf + 16, smf + 32, out + (size_t)(NT + n) * 16);

    } else {
        // ---- devices (8 nodes) ----
        int n = t;
        if (n >= 8) return;
        float acc[16];
#pragma unroll
        for (int h = 0; h < 16; h++) acc[h] = b_rel[2 * 16 + h] + b_rel[4 * 16 + h];
        for (int d = 0; d < 12; d++) {
            float v = g_tdev[n * 12 + d];
#pragma unroll
            for (int h = 0; h < 16; h++) acc[h] += v * W_rel12[1 * 192 + d * 16 + h];
        }
        for (int d = 0; d < 5; d++) {
            float v = g_ddev[n * 8 + d];
#pragma unroll
            for (int h = 0; h < 16; h++) acc[h] += v * W_rel5[80 + d * 16 + h];
        }
        for (int d = 0; d < 12; d++) {
            float v = xv[n * 12 + d];
#pragma unroll
            for (int h = 0; h < 16; h++)
                acc[h] += v * (W_root12[1 * 192 + d * 16 + h] + W_root12[3 * 192 + d * 16 + h]);
        }
        float gam[16], bet[16];
#pragma unroll
        for (int h = 0; h < 16; h++) { gam[h] = ln_g[2 * 16 + h]; bet[h] = ln_b[2 * 16 + h]; }
        ln_act_store(acc, gam, bet, out + (size_t)(NT + ND + n) * 16);
    }
}

// ---------------- launch ----------------
extern "C" void kernel_launch(void* const* d_in, const int* in_sizes, int n_in,
                              void* d_out, int out_size) {
    const float* x_tasks = (const float*)d_in[0];
    const float* x_data  = (const float*)d_in[1];
    const float* x_dev   = (const float*)d_in[2];
    const int* ei_dt   = (const int*)d_in[3];   // data  -> tasks
    const int* ei_td   = (const int*)d_in[4];   // tasks -> data
    const int* ei_tdev = (const int*)d_in[5];   // tasks -> devices
    const int* ei_devt = (const int*)d_in[6];   // devices -> tasks
    const int* ei_ddev = (const int*)d_in[7];   // data  -> devices
    const int* ei_devd = (const int*)d_in[8];   // devices -> data
    const int* ei_tto  = (const int*)d_in[9];   // tasks -> tasks (to)
    const int* ei_ttf  = (const int*)d_in[10];  // tasks -> tasks (from)
    const float* W_rel5   = (const float*)d_in[11];
    const float* W_rel12  = (const float*)d_in[12];
    const float* b_rel    = (const float*)d_in[13];
    const float* W_root5  = (const float*)d_in[14];
    const float* W_root12 = (const float*)d_in[15];
    const float* ln_g     = (const float*)d_in[16];
    const float* ln_b     = (const float*)d_in[17];
    float* out = (float*)d_out;

    int E_dt   = in_sizes[3]  / 2;
    int E_td   = in_sizes[4]  / 2;
    int E_tdev = in_sizes[5]  / 2;
    int E_devt = in_sizes[6]  / 2;
    int E_ddev = in_sizes[7]  / 2;
    int E_devd = in_sizes[8]  / 2;
    int E_tto  = in_sizes[9]  / 2;
    int E_ttf  = in_sizes[10] / 2;

    auto cdiv = [](int a, int b) { return (a + b - 1) / b; };
    int b0 = cdiv(E_dt, 256);
    int b1 = b0 + cdiv(E_tto, 256);
    int b2 = b1 + cdiv(E_ttf, 256);
    int b3 = b2 + cdiv(E_td, 256);
    int b4 = b3 + cdiv(E_devt, 256);
    int b5 = b4 + cdiv(E_devd, 256);
    int b6 = b5 + cdiv(E_tdev, 256);
    int b7 = b6 + cdiv(E_ddev, 256);

    prep<<<1024, 256>>>(x_data);
    fused_scatter<<<b7, 256>>>(x_tasks,
                               ei_dt, E_dt, ei_tto, E_tto, ei_ttf, E_ttf, ei_td, E_td,
                               ei_devt, E_devt, ei_devd, E_devd,
                               ei_tdev, E_tdev, ei_ddev, E_ddev,
                               b0, b1, b2, b3, b4, b5, b6);
    fused_node<<<NBT + NBD + 1, 256>>>(x_tasks, x_dev, W_rel5, W_rel12, b_rel,
                                       W_root5, W_root12, ln_g, ln_b, out);
}